// round 12
// baseline (speedup 1.0000x reference)
#include <cuda_runtime.h>
#include <cuda_fp16.h>
#include <math.h>

#define NN 8192
#define DD 256
#define HH 64

#define PROD_BLOCKS 256   // blocks 0..255 also run the MLP (32 rows each)
#define PROD_ROWS 32

// Pre-scaled features: he[j, d] = e_j * h[j, d], fp16 (4 MB, L2-resident).
__device__ __half g_he[NN * DD];
__device__ int g_done;    // producer completion counter (reset each call)

// ---------------------------------------------------------------------------
// Kernel 0: reset the producer flag (must run before each fused launch).
// ---------------------------------------------------------------------------
__global__ void init_kernel() {
  if (threadIdx.x == 0) g_done = 0;
}

// ---------------------------------------------------------------------------
// Fused kernel: 8192 blocks (one output row each), 256 threads.
// Blocks 0..PROD_BLOCKS-1 first compute the MLP gate for 32 rows:
//   e = sigmoid(relu(h @ W1 + b1) @ W2 + b2);  he = e * h (fp16)
// then ALL blocks run the measured-best agg:
//   scan A row -> register pending mask (independent of he)
//   spin until all producers publish he (tid 0, __nanosleep)
//   gather fp16 he rows (4-wide ballot rounds), fp32 acc, cross-warp reduce.
// ---------------------------------------------------------------------------
__global__ void __launch_bounds__(256, 6) fused_kernel(
    const float* __restrict__ A, const float* __restrict__ h,
    const float* __restrict__ W1, const float* __restrict__ b1,
    const float* __restrict__ W2, const float* __restrict__ b2,
    float* __restrict__ out_h, float* __restrict__ out_e) {

  __shared__ __align__(16) float s_red[8][DD];   // 8 KB (agg reduce)
  __shared__ float sPart[PROD_ROWS][17];         // MLP partials
  __shared__ float sE[PROD_ROWS];

  const int tid = threadIdx.x;
  const int wid = tid >> 5;
  const int lane = tid & 31;
  const int row = blockIdx.x;

  // ======================= producer: MLP for 32 rows =======================
  if (blockIdx.x < PROD_BLOCKS) {
    const int rowbase = blockIdx.x * PROD_ROWS;
    const int rg = tid >> 4;                 // 0..15 -> rows rg*2, rg*2+1
    const int jg = tid & 15;                 // 0..15 -> j jg*4 .. +3
    const int j0 = jg * 4;

    const float4* h4 = (const float4*)h;     // row r = 64 float4
    const float4* W14 = (const float4*)W1;   // row k = 16 float4 over j

    float acc[2][4];
    {
      const float4 b = __ldg((const float4*)(b1 + j0));
      #pragma unroll
      for (int a = 0; a < 2; a++) {
        acc[a][0] = b.x; acc[a][1] = b.y; acc[a][2] = b.z; acc[a][3] = b.w;
      }
    }

    const size_t hbase = (size_t)(rowbase + rg * 2) * (DD / 4);

    #pragma unroll 4
    for (int k4 = 0; k4 < DD / 4; k4++) {
      const float4 hv0 = __ldg(&h4[hbase + k4]);
      const float4 hv1 = __ldg(&h4[hbase + (DD / 4) + k4]);
      const float4 wA = __ldg(&W14[(k4 * 4 + 0) * 16 + jg]);
      const float4 wB = __ldg(&W14[(k4 * 4 + 1) * 16 + jg]);
      const float4 wC = __ldg(&W14[(k4 * 4 + 2) * 16 + jg]);
      const float4 wD = __ldg(&W14[(k4 * 4 + 3) * 16 + jg]);

      acc[0][0] = fmaf(hv0.x, wA.x, fmaf(hv0.y, wB.x, fmaf(hv0.z, wC.x, fmaf(hv0.w, wD.x, acc[0][0]))));
      acc[0][1] = fmaf(hv0.x, wA.y, fmaf(hv0.y, wB.y, fmaf(hv0.z, wC.y, fmaf(hv0.w, wD.y, acc[0][1]))));
      acc[0][2] = fmaf(hv0.x, wA.z, fmaf(hv0.y, wB.z, fmaf(hv0.z, wC.z, fmaf(hv0.w, wD.z, acc[0][2]))));
      acc[0][3] = fmaf(hv0.x, wA.w, fmaf(hv0.y, wB.w, fmaf(hv0.z, wC.w, fmaf(hv0.w, wD.w, acc[0][3]))));
      acc[1][0] = fmaf(hv1.x, wA.x, fmaf(hv1.y, wB.x, fmaf(hv1.z, wC.x, fmaf(hv1.w, wD.x, acc[1][0]))));
      acc[1][1] = fmaf(hv1.x, wA.y, fmaf(hv1.y, wB.y, fmaf(hv1.z, wC.y, fmaf(hv1.w, wD.y, acc[1][1]))));
      acc[1][2] = fmaf(hv1.x, wA.z, fmaf(hv1.y, wB.z, fmaf(hv1.z, wC.z, fmaf(hv1.w, wD.z, acc[1][2]))));
      acc[1][3] = fmaf(hv1.x, wA.w, fmaf(hv1.y, wB.w, fmaf(hv1.z, wC.w, fmaf(hv1.w, wD.w, acc[1][3]))));
    }

    {
      const float4 w2 = __ldg((const float4*)(W2 + j0));
      #pragma unroll
      for (int a = 0; a < 2; a++) {
        sPart[rg * 2 + a][jg] =
            fmaxf(acc[a][0], 0.0f) * w2.x + fmaxf(acc[a][1], 0.0f) * w2.y +
            fmaxf(acc[a][2], 0.0f) * w2.z + fmaxf(acc[a][3], 0.0f) * w2.w;
      }
    }
    __syncthreads();

    if (tid < PROD_ROWS) {
      float s = __ldg(&b2[0]);
      #pragma unroll
      for (int g = 0; g < 16; g++) s += sPart[tid][g];
      const float ev = 1.0f / (1.0f + expf(-s));
      sE[tid] = ev;
      out_e[rowbase + tid] = ev;
    }
    __syncthreads();

    // Emit he16 = e_row * h (h rows L1-hot from the k-loop). 8 float4/thread.
    __half2* he2 = (__half2*)g_he;
    #pragma unroll
    for (int i = tid; i < PROD_ROWS * (DD / 4); i += 256) {
      const int r = i >> 6;
      const float4 hv = __ldg(&h4[(size_t)rowbase * (DD / 4) + i]);
      const float e = sE[r];
      const size_t base = ((size_t)rowbase * DD + i * 4) >> 1;
      he2[base]     = __floats2half2_rn(hv.x * e, hv.y * e);
      he2[base + 1] = __floats2half2_rn(hv.z * e, hv.w * e);
    }

    __syncthreads();                      // all he stores of this block issued
    if (tid == 0) {
      __threadfence();                    // release: he visible before count
      atomicAdd(&g_done, 1);
    }
  }

  // ============================ agg (all blocks) ============================
  const uint4* Aslice = (const uint4*)(A + (size_t)row * NN) + wid * 256;

  // Scan: 8 front-batched streaming loads (DRAM MLP = 8); independent of he.
  uint4 av[8];
  #pragma unroll
  for (int r = 0; r < 8; r++)
    av[r] = __ldcs(Aslice + r * 32 + lane);

  // pending bit (r*4+c) = A[...] > 0 (a > 0 <=> bit pattern != 0).
  unsigned pending = 0u;
  #pragma unroll
  for (int r = 0; r < 8; r++) {
    unsigned f = 0u;
    if (av[r].x) f |= 1u;
    if (av[r].y) f |= 2u;
    if (av[r].z) f |= 4u;
    if (av[r].w) f |= 8u;
    pending |= f << (r * 4);
  }

  // Wait for all producers (tid 0 spins with backoff; others park at BAR).
  if (tid == 0) {
    while (*(volatile int*)&g_done < PROD_BLOCKS) __nanosleep(200);
  }
  __syncthreads();
  __threadfence();   // acquire side: order he reads after flag observation

  const uint4* he4 = (const uint4*)g_he;   // he row = 32 uint4 (256 halves)
  float acc[8] = {0.f, 0.f, 0.f, 0.f, 0.f, 0.f, 0.f, 0.f};

  while (true) {
    unsigned m = __ballot_sync(0xFFFFFFFFu, pending != 0u);
    if (!m) break;

    const int b = __ffs(pending) - 1;
    const int jmine = wid * 1024 + ((b & ~3) << 5) + (lane << 2) + (b & 3);

    const int n = __popc(m) < 4 ? __popc(m) : 4;
    int s0 = __ffs(m) - 1;            m &= m - 1;
    int s1 = m ? __ffs(m) - 1 : s0;   m &= m - 1;
    int s2 = m ? __ffs(m) - 1 : s0;   m &= m - 1;
    int s3 = m ? __ffs(m) - 1 : s0;

    const int j0 = __shfl_sync(0xFFFFFFFFu, jmine, s0);
    const int j1 = __shfl_sync(0xFFFFFFFFu, jmine, s1);
    const int j2 = __shfl_sync(0xFFFFFFFFu, jmine, s2);
    const int j3 = __shfl_sync(0xFFFFFFFFu, jmine, s3);

    if (lane == s0 || (n > 1 && lane == s1) || (n > 2 && lane == s2) ||
        (n > 3 && lane == s3))
      pending &= pending - 1u;

    uint4 v0, v1, v2, v3;
    v0 = __ldg(&he4[(size_t)j0 * 32 + lane]);
    if (n > 1) v1 = __ldg(&he4[(size_t)j1 * 32 + lane]);
    if (n > 2) v2 = __ldg(&he4[(size_t)j2 * 32 + lane]);
    if (n > 3) v3 = __ldg(&he4[(size_t)j3 * 32 + lane]);

    {
      const __half2* p = (const __half2*)&v0;
      #pragma unroll
      for (int q = 0; q < 4; q++) {
        const float2 f = __half22float2(p[q]);
        acc[2 * q] += f.x; acc[2 * q + 1] += f.y;
      }
    }
    if (n > 1) {
      const __half2* p = (const __half2*)&v1;
      #pragma unroll
      for (int q = 0; q < 4; q++) {
        const float2 f = __half22float2(p[q]);
        acc[2 * q] += f.x; acc[2 * q + 1] += f.y;
      }
    }
    if (n > 2) {
      const __half2* p = (const __half2*)&v2;
      #pragma unroll
      for (int q = 0; q < 4; q++) {
        const float2 f = __half22float2(p[q]);
        acc[2 * q] += f.x; acc[2 * q + 1] += f.y;
      }
    }
    if (n > 3) {
      const __half2* p = (const __half2*)&v3;
      #pragma unroll
      for (int q = 0; q < 4; q++) {
        const float2 f = __half22float2(p[q]);
        acc[2 * q] += f.x; acc[2 * q + 1] += f.y;
      }
    }
  }

  {
    float4* rr = (float4*)s_red[wid];
    rr[lane * 2]     = make_float4(acc[0], acc[1], acc[2], acc[3]);
    rr[lane * 2 + 1] = make_float4(acc[4], acc[5], acc[6], acc[7]);
  }
  __syncthreads();

  float s = 0.0f;
  #pragma unroll
  for (int w = 0; w < 8; w++) s += s_red[w][tid];
  out_h[(size_t)row * DD + tid] = s;
}

// ---------------------------------------------------------------------------
// Inputs (setup_inputs order):
//   0: graph_info [N*N], 1: h [N*D], 2: W1 [D*H], 3: b1 [H], 4: W2 [H], 5: b2 [1]
// Output: h_out [N*D] followed by e [N].
// ---------------------------------------------------------------------------
extern "C" void kernel_launch(void* const* d_in, const int* in_sizes, int n_in,
                              void* d_out, int out_size) {
  const float* A  = (const float*)d_in[0];
  const float* h  = (const float*)d_in[1];
  const float* W1 = (const float*)d_in[2];
  const float* b1 = (const float*)d_in[3];
  const float* W2 = (const float*)d_in[4];
  const float* b2 = (const float*)d_in[5];

  float* out_h = (float*)d_out;                     // [N*D]
  float* out_e = (float*)d_out + (size_t)NN * DD;   // [N]

  init_kernel<<<1, 32>>>();
  fused_kernel<<<NN, 256>>>(A, h, W1, b1, W2, b2, out_h, out_e);
}

// round 13
// speedup vs baseline: 1.1530x; 1.1530x over previous
#include <cuda_runtime.h>
#include <cuda_fp16.h>
#include <math.h>

#define NN 8192
#define DD 256
#define HH 64

// Pre-scaled features: he[j, d] = e_j * h[j, d], fp16 (4 MB, L2-resident).
__device__ __half g_he[NN * DD];

// ---------------------------------------------------------------------------
// Kernel 1: e = sigmoid(relu(h @ W1 + b1) @ W2 + b2); emit he = e*h (fp16).
// 8 rows/block -> 1024 blocks (~7/SM, 28 warps/SM for latency hiding).
// 128 threads = 8 rowgroups(1 row) x 16 jgroups(x4 j).
// Per k4: 1 broadcast LDS.128 + 4 float4 W1 LDG + 16 FFMA.
// ---------------------------------------------------------------------------
#define MLP_ROWS 8
__global__ void __launch_bounds__(128) mlp_kernel(
    const float* __restrict__ h, const float* __restrict__ W1,
    const float* __restrict__ b1, const float* __restrict__ W2,
    const float* __restrict__ b2, float* __restrict__ out_e) {

  __shared__ __align__(16) float sh_h[MLP_ROWS * DD];   // 8 KB
  __shared__ float sPart[MLP_ROWS][17];
  __shared__ float sE[MLP_ROWS];

  const int tid = threadIdx.x;
  const int rg = tid >> 4;                  // 0..7 -> local row
  const int jg = tid & 15;                  // 0..15 -> j jg*4 .. +3
  const int j0 = jg * 4;
  const int rowbase = blockIdx.x * MLP_ROWS;

  // Stage 8 h rows (512 float4 / 128 thr = 4 each), coalesced.
  {
    const float4* src = (const float4*)(h + (size_t)rowbase * DD);
    float4* dst = (float4*)sh_h;
    #pragma unroll
    for (int i = tid; i < MLP_ROWS * DD / 4; i += 128) dst[i] = __ldg(&src[i]);
  }
  __syncthreads();

  float acc0, acc1, acc2, acc3;
  {
    const float4 b = __ldg((const float4*)(b1 + j0));
    acc0 = b.x; acc1 = b.y; acc2 = b.z; acc3 = b.w;
  }

  const float4* sh4 = (const float4*)sh_h;
  const float4* W14 = (const float4*)W1;    // row k = 16 float4 over j

  #pragma unroll 4
  for (int k4 = 0; k4 < DD / 4; k4++) {
    const float4 hv = sh4[rg * (DD / 4) + k4];          // 16-way broadcast
    const float4 wA = __ldg(&W14[(k4 * 4 + 0) * 16 + jg]);
    const float4 wB = __ldg(&W14[(k4 * 4 + 1) * 16 + jg]);
    const float4 wC = __ldg(&W14[(k4 * 4 + 2) * 16 + jg]);
    const float4 wD = __ldg(&W14[(k4 * 4 + 3) * 16 + jg]);

    acc0 = fmaf(hv.x, wA.x, fmaf(hv.y, wB.x, fmaf(hv.z, wC.x, fmaf(hv.w, wD.x, acc0))));
    acc1 = fmaf(hv.x, wA.y, fmaf(hv.y, wB.y, fmaf(hv.z, wC.y, fmaf(hv.w, wD.y, acc1))));
    acc2 = fmaf(hv.x, wA.z, fmaf(hv.y, wB.z, fmaf(hv.z, wC.z, fmaf(hv.w, wD.z, acc2))));
    acc3 = fmaf(hv.x, wA.w, fmaf(hv.y, wB.w, fmaf(hv.z, wC.w, fmaf(hv.w, wD.w, acc3))));
  }

  {
    const float4 w2 = __ldg((const float4*)(W2 + j0));
    sPart[rg][jg] = fmaxf(acc0, 0.0f) * w2.x + fmaxf(acc1, 0.0f) * w2.y +
                    fmaxf(acc2, 0.0f) * w2.z + fmaxf(acc3, 0.0f) * w2.w;
  }
  __syncthreads();

  if (tid < MLP_ROWS) {
    float s = __ldg(&b2[0]);
    #pragma unroll
    for (int g = 0; g < 16; g++) s += sPart[tid][g];
    const float ev = 1.0f / (1.0f + expf(-s));
    sE[tid] = ev;
    out_e[rowbase + tid] = ev;
  }
  __syncthreads();

  // Emit he16 = e_row * h from smem (4 float4 per thread).
  __half2* he2 = (__half2*)g_he;
  #pragma unroll
  for (int i = tid; i < MLP_ROWS * (DD / 4); i += 128) {
    const int r = i >> 6;
    const float4 hv = ((const float4*)sh_h)[i];
    const float e = sE[r];
    const size_t base = ((size_t)rowbase * DD + i * 4) >> 1;
    he2[base]     = __floats2half2_rn(hv.x * e, hv.y * e);
    he2[base + 1] = __floats2half2_rn(hv.z * e, hv.w * e);
  }
}

// ---------------------------------------------------------------------------
// Kernel 2 (EXACT R10 agg — measured 50.75 us, 40 regs, occ 71%):
// h_out[i,:] = sum_{j: A[i,j] > 0} he[j,:]
// One block (8 warps) per row; each warp independent on its 1/8 slice:
//   scan: 8 front-batched __ldcs uint4 -> 32-bit register pending mask
//   gather: per round, 1 ballot picks up to 4 source lanes; shfl their j's;
//           4 independent warp-LDG.128 of fp16 he rows; owners clear a bit.
// Single __syncthreads per row (cross-warp reduce).
// ---------------------------------------------------------------------------
__global__ void __launch_bounds__(256) agg_kernel(const float* __restrict__ A,
                                                  float* __restrict__ out) {
  __shared__ __align__(16) float s_red[8][DD];   // 8 KB

  const int row = blockIdx.x;
  const int tid = threadIdx.x;
  const int wid = tid >> 5;
  const int lane = tid & 31;

  const uint4* Aslice = (const uint4*)(A + (size_t)row * NN) + wid * 256;

  uint4 av[8];
  #pragma unroll
  for (int r = 0; r < 8; r++)
    av[r] = __ldcs(Aslice + r * 32 + lane);

  unsigned pending = 0u;
  #pragma unroll
  for (int r = 0; r < 8; r++) {
    unsigned f = 0u;
    if (av[r].x) f |= 1u;
    if (av[r].y) f |= 2u;
    if (av[r].z) f |= 4u;
    if (av[r].w) f |= 8u;
    pending |= f << (r * 4);
  }

  const uint4* he4 = (const uint4*)g_he;
  float acc[8] = {0.f, 0.f, 0.f, 0.f, 0.f, 0.f, 0.f, 0.f};

  while (true) {
    unsigned m = __ballot_sync(0xFFFFFFFFu, pending != 0u);
    if (!m) break;

    const int b = __ffs(pending) - 1;
    const int jmine = wid * 1024 + ((b & ~3) << 5) + (lane << 2) + (b & 3);

    const int n = __popc(m) < 4 ? __popc(m) : 4;
    int s0 = __ffs(m) - 1;            m &= m - 1;
    int s1 = m ? __ffs(m) - 1 : s0;   m &= m - 1;
    int s2 = m ? __ffs(m) - 1 : s0;   m &= m - 1;
    int s3 = m ? __ffs(m) - 1 : s0;

    const int j0 = __shfl_sync(0xFFFFFFFFu, jmine, s0);
    const int j1 = __shfl_sync(0xFFFFFFFFu, jmine, s1);
    const int j2 = __shfl_sync(0xFFFFFFFFu, jmine, s2);
    const int j3 = __shfl_sync(0xFFFFFFFFu, jmine, s3);

    if (lane == s0 || (n > 1 && lane == s1) || (n > 2 && lane == s2) ||
        (n > 3 && lane == s3))
      pending &= pending - 1u;

    uint4 v0, v1, v2, v3;
    v0 = __ldg(&he4[(size_t)j0 * 32 + lane]);
    if (n > 1) v1 = __ldg(&he4[(size_t)j1 * 32 + lane]);
    if (n > 2) v2 = __ldg(&he4[(size_t)j2 * 32 + lane]);
    if (n > 3) v3 = __ldg(&he4[(size_t)j3 * 32 + lane]);

    {
      const __half2* p = (const __half2*)&v0;
      #pragma unroll
      for (int q = 0; q < 4; q++) {
        const float2 f = __half22float2(p[q]);
        acc[2 * q] += f.x; acc[2 * q + 1] += f.y;
      }
    }
    if (n > 1) {
      const __half2* p = (const __half2*)&v1;
      #pragma unroll
      for (int q = 0; q < 4; q++) {
        const float2 f = __half22float2(p[q]);
        acc[2 * q] += f.x; acc[2 * q + 1] += f.y;
      }
    }
    if (n > 2) {
      const __half2* p = (const __half2*)&v2;
      #pragma unroll
      for (int q = 0; q < 4; q++) {
        const float2 f = __half22float2(p[q]);
        acc[2 * q] += f.x; acc[2 * q + 1] += f.y;
      }
    }
    if (n > 3) {
      const __half2* p = (const __half2*)&v3;
      #pragma unroll
      for (int q = 0; q < 4; q++) {
        const float2 f = __half22float2(p[q]);
        acc[2 * q] += f.x; acc[2 * q + 1] += f.y;
      }
    }
  }

  {
    float4* rr = (float4*)s_red[wid];
    rr[lane * 2]     = make_float4(acc[0], acc[1], acc[2], acc[3]);
    rr[lane * 2 + 1] = make_float4(acc[4], acc[5], acc[6], acc[7]);
  }
  __syncthreads();

  float s = 0.0f;
  #pragma unroll
  for (int w = 0; w < 8; w++) s += s_red[w][tid];
  out[(size_t)row * DD + tid] = s;
}

// ---------------------------------------------------------------------------
// Inputs (setup_inputs order):
//   0: graph_info [N*N], 1: h [N*D], 2: W1 [D*H], 3: b1 [H], 4: W2 [H], 5: b2 [1]
// Output: h_out [N*D] followed by e [N].
// ---------------------------------------------------------------------------
extern "C" void kernel_launch(void* const* d_in, const int* in_sizes, int n_in,
                              void* d_out, int out_size) {
  const float* A  = (const float*)d_in[0];
  const float* h  = (const float*)d_in[1];
  const float* W1 = (const float*)d_in[2];
  const float* b1 = (const float*)d_in[3];
  const float* W2 = (const float*)d_in[4];
  const float* b2 = (const float*)d_in[5];

  float* out_h = (float*)d_out;                     // [N*D]
  float* out_e = (float*)d_out + (size_t)NN * DD;   // [N]

  mlp_kernel<<<NN / MLP_ROWS, 128>>>(h, W1, b1, W2, b2, out_e);
  agg_kernel<<<NN, 256>>>(A, out_h);
}

// round 14
// speedup vs baseline: 1.1869x; 1.0294x over previous
#include <cuda_runtime.h>
#include <cuda_fp16.h>
#include <math.h>

#define NN 8192
#define DD 256
#define HH 64

// Pre-scaled features: he[j, d] = e_j * h[j, d], fp16 (4 MB, L2-resident).
__device__ __half g_he[NN * DD];

// ---------------------------------------------------------------------------
// Kernel 1: e = sigmoid(relu(h @ W1 + b1) @ W2 + b2); emit he = e*h (fp16).
// 16 rows/block -> 512 blocks (~3.5/SM, 14 warps/SM), 128 threads.
// Thread tile 2 rows x 4 j: per k4 = 2 broadcast LDS.128 + 4 W1 float4 LDG
// (L1-resident) + 32 FFMA. Warp-LDG total 524K (~3.6us LSU issue).
// ---------------------------------------------------------------------------
#define MLP_ROWS 16
__global__ void __launch_bounds__(128) mlp_kernel(
    const float* __restrict__ h, const float* __restrict__ W1,
    const float* __restrict__ b1, const float* __restrict__ W2,
    const float* __restrict__ b2, float* __restrict__ out_e) {

  __shared__ __align__(16) float sh_h[MLP_ROWS * DD];   // 16 KB
  __shared__ float sPart[MLP_ROWS][17];
  __shared__ float sE[MLP_ROWS];

  const int tid = threadIdx.x;
  const int rg = tid >> 4;                  // 0..7 -> rows rg*2, rg*2+1
  const int jg = tid & 15;                  // 0..15 -> j jg*4 .. +3
  const int j0 = jg * 4;
  const int rowbase = blockIdx.x * MLP_ROWS;

  // Stage 16 h rows (1024 float4 / 128 thr = 8 each), coalesced.
  {
    const float4* src = (const float4*)(h + (size_t)rowbase * DD);
    float4* dst = (float4*)sh_h;
    #pragma unroll
    for (int i = tid; i < MLP_ROWS * DD / 4; i += 128) dst[i] = __ldg(&src[i]);
  }
  __syncthreads();

  float acc[2][4];
  {
    const float4 b = __ldg((const float4*)(b1 + j0));
    #pragma unroll
    for (int a = 0; a < 2; a++) {
      acc[a][0] = b.x; acc[a][1] = b.y; acc[a][2] = b.z; acc[a][3] = b.w;
    }
  }

  const float4* sh4 = (const float4*)sh_h;
  const float4* W14 = (const float4*)W1;    // row k = 16 float4 over j

  #pragma unroll 4
  for (int k4 = 0; k4 < DD / 4; k4++) {
    const float4 hv0 = sh4[(rg * 2 + 0) * (DD / 4) + k4];   // broadcast
    const float4 hv1 = sh4[(rg * 2 + 1) * (DD / 4) + k4];
    const float4 wA = __ldg(&W14[(k4 * 4 + 0) * 16 + jg]);
    const float4 wB = __ldg(&W14[(k4 * 4 + 1) * 16 + jg]);
    const float4 wC = __ldg(&W14[(k4 * 4 + 2) * 16 + jg]);
    const float4 wD = __ldg(&W14[(k4 * 4 + 3) * 16 + jg]);

    acc[0][0] = fmaf(hv0.x, wA.x, fmaf(hv0.y, wB.x, fmaf(hv0.z, wC.x, fmaf(hv0.w, wD.x, acc[0][0]))));
    acc[0][1] = fmaf(hv0.x, wA.y, fmaf(hv0.y, wB.y, fmaf(hv0.z, wC.y, fmaf(hv0.w, wD.y, acc[0][1]))));
    acc[0][2] = fmaf(hv0.x, wA.z, fmaf(hv0.y, wB.z, fmaf(hv0.z, wC.z, fmaf(hv0.w, wD.z, acc[0][2]))));
    acc[0][3] = fmaf(hv0.x, wA.w, fmaf(hv0.y, wB.w, fmaf(hv0.z, wC.w, fmaf(hv0.w, wD.w, acc[0][3]))));
    acc[1][0] = fmaf(hv1.x, wA.x, fmaf(hv1.y, wB.x, fmaf(hv1.z, wC.x, fmaf(hv1.w, wD.x, acc[1][0]))));
    acc[1][1] = fmaf(hv1.x, wA.y, fmaf(hv1.y, wB.y, fmaf(hv1.z, wC.y, fmaf(hv1.w, wD.y, acc[1][1]))));
    acc[1][2] = fmaf(hv1.x, wA.z, fmaf(hv1.y, wB.z, fmaf(hv1.z, wC.z, fmaf(hv1.w, wD.z, acc[1][2]))));
    acc[1][3] = fmaf(hv1.x, wA.w, fmaf(hv1.y, wB.w, fmaf(hv1.z, wC.w, fmaf(hv1.w, wD.w, acc[1][3]))));
  }

  {
    const float4 w2 = __ldg((const float4*)(W2 + j0));
    #pragma unroll
    for (int a = 0; a < 2; a++) {
      sPart[rg * 2 + a][jg] =
          fmaxf(acc[a][0], 0.0f) * w2.x + fmaxf(acc[a][1], 0.0f) * w2.y +
          fmaxf(acc[a][2], 0.0f) * w2.z + fmaxf(acc[a][3], 0.0f) * w2.w;
    }
  }
  __syncthreads();

  if (tid < MLP_ROWS) {
    float s = __ldg(&b2[0]);
    #pragma unroll
    for (int g = 0; g < 16; g++) s += sPart[tid][g];
    const float ev = 1.0f / (1.0f + expf(-s));
    sE[tid] = ev;
    out_e[rowbase + tid] = ev;
  }
  __syncthreads();

  // Emit he16 = e_row * h from smem (8 float4 per thread).
  __half2* he2 = (__half2*)g_he;
  #pragma unroll
  for (int i = tid; i < MLP_ROWS * (DD / 4); i += 128) {
    const int r = i >> 6;
    const float4 hv = ((const float4*)sh_h)[i];
    const float e = sE[r];
    const size_t base = ((size_t)rowbase * DD + i * 4) >> 1;
    he2[base]     = __floats2half2_rn(hv.x * e, hv.y * e);
    he2[base + 1] = __floats2half2_rn(hv.z * e, hv.w * e);
  }
}

// ---------------------------------------------------------------------------
// Kernel 2 (EXACT R10 agg — measured 50.75 us, 40 regs, occ 71%):
// h_out[i,:] = sum_{j: A[i,j] > 0} he[j,:]
// One block (8 warps) per row; each warp independent on its 1/8 slice:
//   scan: 8 front-batched __ldcs uint4 -> 32-bit register pending mask
//   gather: per round, 1 ballot picks up to 4 source lanes; shfl their j's;
//           4 independent warp-LDG.128 of fp16 he rows; owners clear a bit.
// Single __syncthreads per row (cross-warp reduce).
// ---------------------------------------------------------------------------
__global__ void __launch_bounds__(256) agg_kernel(const float* __restrict__ A,
                                                  float* __restrict__ out) {
  __shared__ __align__(16) float s_red[8][DD];   // 8 KB

  const int row = blockIdx.x;
  const int tid = threadIdx.x;
  const int wid = tid >> 5;
  const int lane = tid & 31;

  const uint4* Aslice = (const uint4*)(A + (size_t)row * NN) + wid * 256;

  uint4 av[8];
  #pragma unroll
  for (int r = 0; r < 8; r++)
    av[r] = __ldcs(Aslice + r * 32 + lane);

  unsigned pending = 0u;
  #pragma unroll
  for (int r = 0; r < 8; r++) {
    unsigned f = 0u;
    if (av[r].x) f |= 1u;
    if (av[r].y) f |= 2u;
    if (av[r].z) f |= 4u;
    if (av[r].w) f |= 8u;
    pending |= f << (r * 4);
  }

  const uint4* he4 = (const uint4*)g_he;
  float acc[8] = {0.f, 0.f, 0.f, 0.f, 0.f, 0.f, 0.f, 0.f};

  while (true) {
    unsigned m = __ballot_sync(0xFFFFFFFFu, pending != 0u);
    if (!m) break;

    const int b = __ffs(pending) - 1;
    const int jmine = wid * 1024 + ((b & ~3) << 5) + (lane << 2) + (b & 3);

    const int n = __popc(m) < 4 ? __popc(m) : 4;
    int s0 = __ffs(m) - 1;            m &= m - 1;
    int s1 = m ? __ffs(m) - 1 : s0;   m &= m - 1;
    int s2 = m ? __ffs(m) - 1 : s0;   m &= m - 1;
    int s3 = m ? __ffs(m) - 1 : s0;

    const int j0 = __shfl_sync(0xFFFFFFFFu, jmine, s0);
    const int j1 = __shfl_sync(0xFFFFFFFFu, jmine, s1);
    const int j2 = __shfl_sync(0xFFFFFFFFu, jmine, s2);
    const int j3 = __shfl_sync(0xFFFFFFFFu, jmine, s3);

    if (lane == s0 || (n > 1 && lane == s1) || (n > 2 && lane == s2) ||
        (n > 3 && lane == s3))
      pending &= pending - 1u;

    uint4 v0, v1, v2, v3;
    v0 = __ldg(&he4[(size_t)j0 * 32 + lane]);
    if (n > 1) v1 = __ldg(&he4[(size_t)j1 * 32 + lane]);
    if (n > 2) v2 = __ldg(&he4[(size_t)j2 * 32 + lane]);
    if (n > 3) v3 = __ldg(&he4[(size_t)j3 * 32 + lane]);

    {
      const __half2* p = (const __half2*)&v0;
      #pragma unroll
      for (int q = 0; q < 4; q++) {
        const float2 f = __half22float2(p[q]);
        acc[2 * q] += f.x; acc[2 * q + 1] += f.y;
      }
    }
    if (n > 1) {
      const __half2* p = (const __half2*)&v1;
      #pragma unroll
      for (int q = 0; q < 4; q++) {
        const float2 f = __half22float2(p[q]);
        acc[2 * q] += f.x; acc[2 * q + 1] += f.y;
      }
    }
    if (n > 2) {
      const __half2* p = (const __half2*)&v2;
      #pragma unroll
      for (int q = 0; q < 4; q++) {
        const float2 f = __half22float2(p[q]);
        acc[2 * q] += f.x; acc[2 * q + 1] += f.y;
      }
    }
    if (n > 3) {
      const __half2* p = (const __half2*)&v3;
      #pragma unroll
      for (int q = 0; q < 4; q++) {
        const float2 f = __half22float2(p[q]);
        acc[2 * q] += f.x; acc[2 * q + 1] += f.y;
      }
    }
  }

  {
    float4* rr = (float4*)s_red[wid];
    rr[lane * 2]     = make_float4(acc[0], acc[1], acc[2], acc[3]);
    rr[lane * 2 + 1] = make_float4(acc[4], acc[5], acc[6], acc[7]);
  }
  __syncthreads();

  float s = 0.0f;
  #pragma unroll
  for (int w = 0; w < 8; w++) s += s_red[w][tid];
  out[(size_t)row * DD + tid] = s;
}

// ---------------------------------------------------------------------------
// Inputs (setup_inputs order):
//   0: graph_info [N*N], 1: h [N*D], 2: W1 [D*H], 3: b1 [H], 4: W2 [H], 5: b2 [1]
// Output: h_out [N*D] followed by e [N].
// ---------------------------------------------------------------------------
extern "C" void kernel_launch(void* const* d_in, const int* in_sizes, int n_in,
                              void* d_out, int out_size) {
  const float* A  = (const float*)d_in[0];
  const float* h  = (const float*)d_in[1];
  const float* W1 = (const float*)d_in[2];
  const float* b1 = (const float*)d_in[3];
  const float* W2 = (const float*)d_in[4];
  const float* b2 = (const float*)d_in[5];

  float* out_h = (float*)d_out;                     // [N*D]
  float* out_e = (float*)d_out + (size_t)NN * DD;   // [N]

  mlp_kernel<<<NN / MLP_ROWS, 128>>>(h, W1, b1, W2, b2, out_e);
  agg_kernel<<<NN, 256>>>(A, out_h);
}

// round 15
// speedup vs baseline: 1.3359x; 1.1256x over previous
#include <cuda_runtime.h>
#include <cuda_fp16.h>
#include <math.h>

#define NN 8192
#define DD 256
#define HH 64

// Pre-scaled features: he[j, d] = e_j * h[j, d], fp16 (4 MB, L2-resident).
__device__ __half g_he[NN * DD];

// ---------------------------------------------------------------------------
// Kernel 1: e = sigmoid(relu(h @ W1 + b1) @ W2 + b2); emit he = e*h (fp16).
// K-SPLIT 4x4 tile: 16 rows/block, 512 blocks, 128 threads =
//   kh (2 k-halves) x rg (4 rowgroups x4 rows) x jg (16 jgroups x4 j).
// Per thread: 32 k4 x (4 broadcast LDS.128 + 4 W1 float4 LDG + 64 FFMA).
// Same total FFMA/LDG as the measured-best R10 tile, but 2x warps/SM.
// Halves combine via smem BEFORE relu.
// ---------------------------------------------------------------------------
#define MLP_ROWS 16
__global__ void __launch_bounds__(128) mlp_kernel(
    const float* __restrict__ h, const float* __restrict__ W1,
    const float* __restrict__ b1, const float* __restrict__ W2,
    const float* __restrict__ b2, float* __restrict__ out_e) {

  __shared__ __align__(16) float sh_h[MLP_ROWS * DD];       // 16 KB
  __shared__ __align__(16) float4 sAcc[2][MLP_ROWS][16];    // 8 KB partials
  __shared__ float sPart[MLP_ROWS][17];
  __shared__ float sE[MLP_ROWS];

  const int tid = threadIdx.x;
  const int kh = tid >> 6;                  // 0..1 -> k half
  const int rg = (tid >> 4) & 3;            // 0..3 -> rows rg*4 .. +3
  const int jg = tid & 15;                  // 0..15 -> j jg*4 .. +3
  const int j0 = jg * 4;
  const int rowbase = blockIdx.x * MLP_ROWS;

  // Stage 16 h rows (1024 float4 / 128 thr = 8 each), coalesced.
  {
    const float4* src = (const float4*)(h + (size_t)rowbase * DD);
    float4* dst = (float4*)sh_h;
    #pragma unroll
    for (int i = tid; i < MLP_ROWS * DD / 4; i += 128) dst[i] = __ldg(&src[i]);
  }
  __syncthreads();

  float acc[4][4];
  if (kh == 0) {
    const float4 b = __ldg((const float4*)(b1 + j0));
    #pragma unroll
    for (int a = 0; a < 4; a++) {
      acc[a][0] = b.x; acc[a][1] = b.y; acc[a][2] = b.z; acc[a][3] = b.w;
    }
  } else {
    #pragma unroll
    for (int a = 0; a < 4; a++)
      #pragma unroll
      for (int c = 0; c < 4; c++) acc[a][c] = 0.0f;
  }

  const float4* sh4 = (const float4*)sh_h;
  const float4* W14 = (const float4*)W1;    // row k = 16 float4 over j

  #pragma unroll 4
  for (int k4 = 0; k4 < 32; k4++) {
    const int kg = kh * 32 + k4;
    float4 hv[4];
    #pragma unroll
    for (int a = 0; a < 4; a++)
      hv[a] = sh4[(rg * 4 + a) * (DD / 4) + kg];          // broadcast

    const float4 wA = __ldg(&W14[(kg * 4 + 0) * 16 + jg]);
    const float4 wB = __ldg(&W14[(kg * 4 + 1) * 16 + jg]);
    const float4 wC = __ldg(&W14[(kg * 4 + 2) * 16 + jg]);
    const float4 wD = __ldg(&W14[(kg * 4 + 3) * 16 + jg]);

    #pragma unroll
    for (int a = 0; a < 4; a++) {
      acc[a][0] = fmaf(hv[a].x, wA.x, fmaf(hv[a].y, wB.x, fmaf(hv[a].z, wC.x, fmaf(hv[a].w, wD.x, acc[a][0]))));
      acc[a][1] = fmaf(hv[a].x, wA.y, fmaf(hv[a].y, wB.y, fmaf(hv[a].z, wC.y, fmaf(hv[a].w, wD.y, acc[a][1]))));
      acc[a][2] = fmaf(hv[a].x, wA.z, fmaf(hv[a].y, wB.z, fmaf(hv[a].z, wC.z, fmaf(hv[a].w, wD.z, acc[a][2]))));
      acc[a][3] = fmaf(hv[a].x, wA.w, fmaf(hv[a].y, wB.w, fmaf(hv[a].z, wC.w, fmaf(hv[a].w, wD.w, acc[a][3]))));
    }
  }

  // Publish kh=1 partials; kh=0 combines, applies relu and the W2 dot.
  if (kh == 1) {
    #pragma unroll
    for (int a = 0; a < 4; a++)
      sAcc[1][rg * 4 + a][jg] = make_float4(acc[a][0], acc[a][1], acc[a][2], acc[a][3]);
  }
  __syncthreads();

  if (kh == 0) {
    const float4 w2 = __ldg((const float4*)(W2 + j0));
    #pragma unroll
    for (int a = 0; a < 4; a++) {
      const float4 o = sAcc[1][rg * 4 + a][jg];
      const float t0 = acc[a][0] + o.x;
      const float t1 = acc[a][1] + o.y;
      const float t2 = acc[a][2] + o.z;
      const float t3 = acc[a][3] + o.w;
      sPart[rg * 4 + a][jg] =
          fmaxf(t0, 0.0f) * w2.x + fmaxf(t1, 0.0f) * w2.y +
          fmaxf(t2, 0.0f) * w2.z + fmaxf(t3, 0.0f) * w2.w;
    }
  }
  __syncthreads();

  if (tid < MLP_ROWS) {
    float s = __ldg(&b2[0]);
    #pragma unroll
    for (int g = 0; g < 16; g++) s += sPart[tid][g];
    const float ev = 1.0f / (1.0f + expf(-s));
    sE[tid] = ev;
    out_e[rowbase + tid] = ev;
  }
  __syncthreads();

  // Emit he16 = e_row * h from smem (8 float4 per thread).
  __half2* he2 = (__half2*)g_he;
  #pragma unroll
  for (int i = tid; i < MLP_ROWS * (DD / 4); i += 128) {
    const int r = i >> 6;
    const float4 hv = ((const float4*)sh_h)[i];
    const float e = sE[r];
    const size_t base = ((size_t)rowbase * DD + i * 4) >> 1;
    he2[base]     = __floats2half2_rn(hv.x * e, hv.y * e);
    he2[base + 1] = __floats2half2_rn(hv.z * e, hv.w * e);
  }
}

// ---------------------------------------------------------------------------
// Kernel 2 (EXACT R10 agg — measured 50.75/51.2/52.7, 40 regs, occ ~71%):
// h_out[i,:] = sum_{j: A[i,j] > 0} he[j,:]
// One block (8 warps) per row; each warp independent on its 1/8 slice:
//   scan: 8 front-batched __ldcs uint4 -> 32-bit register pending mask
//   gather: per round, 1 ballot picks up to 4 source lanes; shfl their j's;
//           4 independent warp-LDG.128 of fp16 he rows; owners clear a bit.
// Single __syncthreads per row (cross-warp reduce). At the LTS ceiling.
// ---------------------------------------------------------------------------
__global__ void __launch_bounds__(256) agg_kernel(const float* __restrict__ A,
                                                  float* __restrict__ out) {
  __shared__ __align__(16) float s_red[8][DD];   // 8 KB

  const int row = blockIdx.x;
  const int tid = threadIdx.x;
  const int wid = tid >> 5;
  const int lane = tid & 31;

  const uint4* Aslice = (const uint4*)(A + (size_t)row * NN) + wid * 256;

  uint4 av[8];
  #pragma unroll
  for (int r = 0; r < 8; r++)
    av[r] = __ldcs(Aslice + r * 32 + lane);

  unsigned pending = 0u;
  #pragma unroll
  for (int r = 0; r < 8; r++) {
    unsigned f = 0u;
    if (av[r].x) f |= 1u;
    if (av[r].y) f |= 2u;
    if (av[r].z) f |= 4u;
    if (av[r].w) f |= 8u;
    pending |= f << (r * 4);
  }

  const uint4* he4 = (const uint4*)g_he;
  float acc[8] = {0.f, 0.f, 0.f, 0.f, 0.f, 0.f, 0.f, 0.f};

  while (true) {
    unsigned m = __ballot_sync(0xFFFFFFFFu, pending != 0u);
    if (!m) break;

    const int b = __ffs(pending) - 1;
    const int jmine = wid * 1024 + ((b & ~3) << 5) + (lane << 2) + (b & 3);

    const int n = __popc(m) < 4 ? __popc(m) : 4;
    int s0 = __ffs(m) - 1;            m &= m - 1;
    int s1 = m ? __ffs(m) - 1 : s0;   m &= m - 1;
    int s2 = m ? __ffs(m) - 1 : s0;   m &= m - 1;
    int s3 = m ? __ffs(m) - 1 : s0;

    const int j0 = __shfl_sync(0xFFFFFFFFu, jmine, s0);
    const int j1 = __shfl_sync(0xFFFFFFFFu, jmine, s1);
    const int j2 = __shfl_sync(0xFFFFFFFFu, jmine, s2);
    const int j3 = __shfl_sync(0xFFFFFFFFu, jmine, s3);

    if (lane == s0 || (n > 1 && lane == s1) || (n > 2 && lane == s2) ||
        (n > 3 && lane == s3))
      pending &= pending - 1u;

    uint4 v0, v1, v2, v3;
    v0 = __ldg(&he4[(size_t)j0 * 32 + lane]);
    if (n > 1) v1 = __ldg(&he4[(size_t)j1 * 32 + lane]);
    if (n > 2) v2 = __ldg(&he4[(size_t)j2 * 32 + lane]);
    if (n > 3) v3 = __ldg(&he4[(size_t)j3 * 32 + lane]);

    {
      const __half2* p = (const __half2*)&v0;
      #pragma unroll
      for (int q = 0; q < 4; q++) {
        const float2 f = __half22float2(p[q]);
        acc[2 * q] += f.x; acc[2 * q + 1] += f.y;
      }
    }
    if (n > 1) {
      const __half2* p = (const __half2*)&v1;
      #pragma unroll
      for (int q = 0; q < 4; q++) {
        const float2 f = __half22float2(p[q]);
        acc[2 * q] += f.x; acc[2 * q + 1] += f.y;
      }
    }
    if (n > 2) {
      const __half2* p = (const __half2*)&v2;
      #pragma unroll
      for (int q = 0; q < 4; q++) {
        const float2 f = __half22float2(p[q]);
        acc[2 * q] += f.x; acc[2 * q + 1] += f.y;
      }
    }
    if (n > 3) {
      const __half2* p = (const __half2*)&v3;
      #pragma unroll
      for (int q = 0; q < 4; q++) {
        const float2 f = __half22float2(p[q]);
        acc[2 * q] += f.x; acc[2 * q + 1] += f.y;
      }
    }
  }

  {
    float4* rr = (float4*)s_red[wid];
    rr[lane * 2]     = make_float4(acc[0], acc[1], acc[2], acc[3]);
    rr[lane * 2 + 1] = make_float4(acc[4], acc[5], acc[6], acc[7]);
  }
  __syncthreads();

  float s = 0.0f;
  #pragma unroll
  for (int w = 0; w < 8; w++) s += s_red[w][tid];
  out[(size_t)row * DD + tid] = s;
}

// ---------------------------------------------------------------------------
// Inputs (setup_inputs order):
//   0: graph_info [N*N], 1: h [N*D], 2: W1 [D*H], 3: b1 [H], 4: W2 [H], 5: b2 [1]
// Output: h_out [N*D] followed by e [N].
// ---------------------------------------------------------------------------
extern "C" void kernel_launch(void* const* d_in, const int* in_sizes, int n_in,
                              void* d_out, int out_size) {
  const float* A  = (const float*)d_in[0];
  const float* h  = (const float*)d_in[1];
  const float* W1 = (const float*)d_in[2];
  const float* b1 = (const float*)d_in[3];
  const float* W2 = (const float*)d_in[4];
  const float* b2 = (const float*)d_in[5];

  float* out_h = (float*)d_out;                     // [N*D]
  float* out_e = (float*)d_out + (size_t)NN * DD;   // [N]

  mlp_kernel<<<NN / MLP_ROWS, 128>>>(h, W1, b1, W2, b2, out_e);
  agg_kernel<<<NN, 256>>>(A, out_h);
}